// round 13
// baseline (speedup 1.0000x reference)
#include <cuda_runtime.h>
#include <math.h>
#include <stdint.h>

#define EB 262144
#define MP 786432
#define FNB 192
#define DM 256
#define KT 448
#define NST 28            // 448 / 16 k-stages

// ---- scratch ----
__device__ float g_s[(size_t)EB * DM];
__device__ float g_r[(size_t)EB * DM];
__device__ float g_z[(size_t)EB * DM];

// ---------------- helpers ----------------
__device__ __forceinline__ uint32_t smem_u32(const void* p) {
    uint32_t a;
    asm("{ .reg .u64 t; cvta.to.shared.u64 t, %1; cvt.u32.u64 %0, t; }" : "=r"(a) : "l"(p));
    return a;
}
__device__ __forceinline__ uint32_t to_tf32(float f) {
    uint32_t r;
    asm("cvt.rna.tf32.f32 %0, %1;" : "=r"(r) : "f"(f));
    return r;
}
__device__ __forceinline__ void red4(float* p, float a, float b, float c, float d) {
    asm volatile("red.global.add.v4.f32 [%0], {%1,%2,%3,%4};"
                 :: "l"(p), "f"(a), "f"(b), "f"(c), "f"(d) : "memory");
}
__device__ __forceinline__ void cpasync16(uint32_t dst, const void* src) {
    asm volatile("cp.async.cg.shared.global [%0], [%1], 16;" :: "r"(dst), "l"(src) : "memory");
}
#define CP_COMMIT() asm volatile("cp.async.commit_group;" ::: "memory")

__device__ __forceinline__ float sigmoidf_(float x) { return 1.f / (1.f + __expf(-x)); }

#define MMA8(d, a, b)                                                           \
    asm volatile("mma.sync.aligned.m16n8k8.row.col.f32.tf32.tf32.f32 "          \
                 "{%0,%1,%2,%3}, {%4,%5,%6,%7}, {%8,%9}, {%0,%1,%2,%3};"        \
                 : "+f"((d)[0]), "+f"((d)[1]), "+f"((d)[2]), "+f"((d)[3])       \
                 : "r"((a)[0]), "r"((a)[1]), "r"((a)[2]), "r"((a)[3]),          \
                   "r"((b)[0]), "r"((b)[1]))

__global__ void zero_scratch() {
    size_t n4 = ((size_t)EB * DM) / 4;
    float4 z = make_float4(0.f, 0.f, 0.f, 0.f);
    for (size_t i = (size_t)blockIdx.x * blockDim.x + threadIdx.x; i < n4;
         i += (size_t)gridDim.x * blockDim.x) {
        reinterpret_cast<float4*>(g_s)[i] = z;
        reinterpret_cast<float4*>(g_r)[i] = z;
    }
}

// MODE 0: pairs  A=[h_ki | mess[nei]] @ Wr ; epi: sigmoid, v4-red(r*mess -> g_r[src]);
//                plus v4-red(mess -> g_s[src]) pre-pass (n-chunk partitioned)
// MODE 1: bonds  A=[h_ij | g_s] @ Wz ; epi: g_z = sigmoid
// MODE 2: bonds  A=[h_ij | g_r] @ [W;U] ; epi: out = (1-z)*s + z*tanh
template <int MODE>
__global__ __launch_bounds__(256, 2)
void dmpnn_mma(const float* __restrict__ h_ij, const float* __restrict__ h_ki,
               const float* __restrict__ mess,
               const int* __restrict__ src_idx, const int* __restrict__ nei_idx,
               const float* __restrict__ Wz_w, const float* __restrict__ Wz_b,
               const float* __restrict__ Wr_w, const float* __restrict__ Wr_b,
               const float* __restrict__ U_w,
               const float* __restrict__ W_w, const float* __restrict__ W_b,
               float* __restrict__ out)
{
    __shared__ float As[2][128][20];    // [stage][m][k] stride 20 (conflict-free frags)
    __shared__ float Bs[2][16][136];    // [stage][k][n] stride 136
    __shared__ int s_src[128], s_nei[128];

    const int tid  = threadIdx.x;
    const int warp = tid >> 5;
    const int lane = tid & 31;
    const int wr   = warp & 3;          // warp row (4)
    const int wc   = warp >> 2;         // warp col (2)
    const int gid  = lane >> 2;         // 0..7
    const int tig  = lane & 3;          // 0..3
    const int r0   = blockIdx.x * 128;
    const int n0   = blockIdx.y * 128;

    if (MODE == 0 && tid < 128) {
        s_src[tid] = src_idx[r0 + tid];
        s_nei[tid] = nei_idx[r0 + tid];
    }
    __syncthreads();

    const uint32_t aSm[2] = { smem_u32(&As[0][0][0]), smem_u32(&As[1][0][0]) };
    const uint32_t bSm[2] = { smem_u32(&Bs[0][0][0]), smem_u32(&Bs[1][0][0]) };

    // ---- stage fill via cp.async (A: 128x16, B: 16x128) ----
    auto fill = [&](int s) {
        const int st = s & 1;
        const int k0 = s * 16;
#pragma unroll
        for (int i = 0; i < 2; ++i) {
            int idx = tid + 256 * i;
            int row = idx >> 2, kq = idx & 3;
            const float* ap;
            if (MODE == 0)
                ap = (k0 < FNB) ? h_ki + (size_t)(r0 + row) * FNB + k0 + kq * 4
                                : mess + (size_t)s_nei[row] * DM + (k0 - FNB) + kq * 4;
            else if (MODE == 1)
                ap = (k0 < FNB) ? h_ij + (size_t)(r0 + row) * FNB + k0 + kq * 4
                                : g_s + (size_t)(r0 + row) * DM + (k0 - FNB) + kq * 4;
            else
                ap = (k0 < FNB) ? h_ij + (size_t)(r0 + row) * FNB + k0 + kq * 4
                                : g_r + (size_t)(r0 + row) * DM + (k0 - FNB) + kq * 4;
            cpasync16(aSm[st] + row * 80 + kq * 16, ap);
        }
#pragma unroll
        for (int i = 0; i < 2; ++i) {
            int idx = tid + 256 * i;
            int row = idx >> 5, c = idx & 31;
            const float* bp;
            if (MODE == 0)      bp = Wr_w + (size_t)(k0 + row) * DM + n0 + c * 4;
            else if (MODE == 1) bp = Wz_w + (size_t)(k0 + row) * DM + n0 + c * 4;
            else bp = (k0 < FNB) ? W_w + (size_t)(k0 + row) * DM + n0 + c * 4
                                 : U_w + (size_t)(k0 + row - FNB) * DM + n0 + c * 4;
            cpasync16(bSm[st] + row * 544 + c * 16, bp);
        }
        CP_COMMIT();
    };

    float acc[2][8][4];
#pragma unroll
    for (int mt = 0; mt < 2; ++mt)
#pragma unroll
        for (int nt = 0; nt < 8; ++nt)
#pragma unroll
            for (int q = 0; q < 4; ++q) acc[mt][nt][q] = 0.f;

    fill(0);

    if (MODE == 0) {
        // s_ij scatter for cols [n0, n0+128) — overlaps with fill(0) latency
        for (int it = tid; it < 128 * 32; it += 256) {
            int row = it >> 5, c = (it & 31) << 2;
            const float4 v = *(const float4*)(mess + (size_t)s_nei[row] * DM + n0 + c);
            red4(g_s + (size_t)s_src[row] * DM + n0 + c, v.x, v.y, v.z, v.w);
        }
    }

#pragma unroll 1
    for (int s = 0; s < NST; ++s) {
        if (s + 1 < NST) {
            fill(s + 1);
            asm volatile("cp.async.wait_group 1;" ::: "memory");
        } else {
            asm volatile("cp.async.wait_group 0;" ::: "memory");
        }
        __syncthreads();
        const int st = s & 1;
#pragma unroll
        for (int kh = 0; kh < 2; ++kh) {
            const int kk = kh * 8;
            uint32_t af[2][4];
#pragma unroll
            for (int mt = 0; mt < 2; ++mt) {
                int rb = wr * 32 + mt * 16;
                af[mt][0] = to_tf32(As[st][rb + gid][kk + tig]);
                af[mt][1] = to_tf32(As[st][rb + gid + 8][kk + tig]);
                af[mt][2] = to_tf32(As[st][rb + gid][kk + tig + 4]);
                af[mt][3] = to_tf32(As[st][rb + gid + 8][kk + tig + 4]);
            }
            uint32_t bf[8][2];
#pragma unroll
            for (int nt = 0; nt < 8; ++nt) {
                int cb = wc * 64 + nt * 8;
                bf[nt][0] = to_tf32(Bs[st][kk + tig][cb + gid]);
                bf[nt][1] = to_tf32(Bs[st][kk + tig + 4][cb + gid]);
            }
#pragma unroll
            for (int mt = 0; mt < 2; ++mt)
#pragma unroll
                for (int nt = 0; nt < 8; ++nt)
                    MMA8(acc[mt][nt], af[mt], bf[nt]);
        }
        __syncthreads();
    }

    // ---- epilogue ----
    // c0,c1 at (row=gid, cols 2tig,2tig+1), c2,c3 at row=gid+8
#pragma unroll
    for (int mt = 0; mt < 2; ++mt) {
#pragma unroll
        for (int half = 0; half < 2; ++half) {
            const int lr = wr * 32 + mt * 16 + gid + half * 8;  // local row
            const int gm = r0 + lr;
            if (MODE == 0) {
                const float* mrow = mess + (size_t)s_nei[lr] * DM;
                float* rdst = g_r + (size_t)s_src[lr] * DM;
#pragma unroll
                for (int nt = 0; nt < 8; ++nt) {
                    const int n = n0 + wc * 64 + nt * 8 + 2 * tig;
                    float v0 = acc[mt][nt][half * 2 + 0];
                    float v1 = acc[mt][nt][half * 2 + 1];
                    float2 bb = *(const float2*)(Wr_b + n);
                    float2 m2 = *(const float2*)(mrow + n);
                    float p0 = sigmoidf_(v0 + bb.x) * m2.x;
                    float p1 = sigmoidf_(v1 + bb.y) * m2.y;
                    // merge quad neighbors: even-tig lanes issue v4 reds
                    float q0 = __shfl_down_sync(0xffffffffu, p0, 1);
                    float q1 = __shfl_down_sync(0xffffffffu, p1, 1);
                    if ((tig & 1) == 0)
                        red4(rdst + n, p0, p1, q0, q1);
                }
            } else if (MODE == 1) {
#pragma unroll
                for (int nt = 0; nt < 8; ++nt) {
                    const int n = n0 + wc * 64 + nt * 8 + 2 * tig;
                    float2 bb = *(const float2*)(Wz_b + n);
                    float2 zz;
                    zz.x = sigmoidf_(acc[mt][nt][half * 2 + 0] + bb.x);
                    zz.y = sigmoidf_(acc[mt][nt][half * 2 + 1] + bb.y);
                    *(float2*)(g_z + (size_t)gm * DM + n) = zz;
                }
            } else {
#pragma unroll
                for (int nt = 0; nt < 8; ++nt) {
                    const int n = n0 + wc * 64 + nt * 8 + 2 * tig;
                    float2 bb = *(const float2*)(W_b + n);
                    float2 z2 = *(const float2*)(g_z + (size_t)gm * DM + n);
                    float2 s2 = *(const float2*)(g_s + (size_t)gm * DM + n);
                    float2 o;
                    o.x = (1.f - z2.x) * s2.x +
                          z2.x * tanhf(acc[mt][nt][half * 2 + 0] + bb.x);
                    o.y = (1.f - z2.y) * s2.y +
                          z2.y * tanhf(acc[mt][nt][half * 2 + 1] + bb.y);
                    *(float2*)(out + (size_t)gm * DM + n) = o;
                }
            }
        }
    }
}

// ---------------- launch ----------------
extern "C" void kernel_launch(void* const* d_in, const int* in_sizes, int n_in,
                              void* d_out, int out_size) {
    const float* h_ij = (const float*)d_in[0];
    const float* h_ki = (const float*)d_in[1];
    const float* mess = (const float*)d_in[2];
    const int* src_i  = (const int*)d_in[3];
    const int* nei_i  = (const int*)d_in[4];
    const float* Wz_w = (const float*)d_in[5];
    const float* Wz_b = (const float*)d_in[6];
    const float* Wr_w = (const float*)d_in[7];
    const float* Wr_b = (const float*)d_in[8];
    const float* U_w  = (const float*)d_in[9];
    const float* W_w  = (const float*)d_in[10];
    const float* W_b  = (const float*)d_in[11];
    float* out = (float*)d_out;

    zero_scratch<<<1184, 256>>>();

    dim3 g0(MP / 128, 2);
    dmpnn_mma<0><<<g0, 256>>>(h_ij, h_ki, mess, src_i, nei_i,
                              Wz_w, Wz_b, Wr_w, Wr_b, U_w, W_w, W_b, out);
    dim3 g1(EB / 128, 2);
    dmpnn_mma<1><<<g1, 256>>>(h_ij, h_ki, mess, src_i, nei_i,
                              Wz_w, Wz_b, Wr_w, Wr_b, U_w, W_w, W_b, out);
    dmpnn_mma<2><<<g1, 256>>>(h_ij, h_ki, mess, src_i, nei_i,
                              Wz_w, Wz_b, Wr_w, Wr_b, U_w, W_w, W_b, out);
}

// round 14
// speedup vs baseline: 1.0040x; 1.0040x over previous
#include <cuda_runtime.h>
#include <math.h>
#include <stdint.h>

#define EB 262144
#define MP 786432
#define FNB 192
#define DM 256
#define KT 448
#define NST 28            // 448 / 16 k-stages

// ---- scratch ----
__device__ float g_s[(size_t)EB * DM];
__device__ float g_r[(size_t)EB * DM];
__device__ float g_z[(size_t)EB * DM];

// ---------------- helpers ----------------
__device__ __forceinline__ uint32_t smem_u32(const void* p) {
    uint32_t a;
    asm("{ .reg .u64 t; cvta.to.shared.u64 t, %1; cvt.u32.u64 %0, t; }" : "=r"(a) : "l"(p));
    return a;
}
__device__ __forceinline__ uint32_t to_tf32(float f) {
    uint32_t r;
    asm("cvt.rna.tf32.f32 %0, %1;" : "=r"(r) : "f"(f));
    return r;
}
__device__ __forceinline__ void red4(float* p, float a, float b, float c, float d) {
    asm volatile("red.global.add.v4.f32 [%0], {%1,%2,%3,%4};"
                 :: "l"(p), "f"(a), "f"(b), "f"(c), "f"(d) : "memory");
}
__device__ __forceinline__ void cpasync16(uint32_t dst, const void* src) {
    asm volatile("cp.async.cg.shared.global [%0], [%1], 16;" :: "r"(dst), "l"(src) : "memory");
}
#define CP_COMMIT() asm volatile("cp.async.commit_group;" ::: "memory")

__device__ __forceinline__ float sigmoidf_(float x) { return 1.f / (1.f + __expf(-x)); }

#define MMA8(d, a, b)                                                           \
    asm volatile("mma.sync.aligned.m16n8k8.row.col.f32.tf32.tf32.f32 "          \
                 "{%0,%1,%2,%3}, {%4,%5,%6,%7}, {%8,%9}, {%0,%1,%2,%3};"        \
                 : "+f"((d)[0]), "+f"((d)[1]), "+f"((d)[2]), "+f"((d)[3])       \
                 : "r"((a)[0]), "r"((a)[1]), "r"((a)[2]), "r"((a)[3]),          \
                   "r"((b)[0]), "r"((b)[1]))

__global__ void zero_scratch() {
    size_t n4 = ((size_t)EB * DM) / 4;
    float4 z = make_float4(0.f, 0.f, 0.f, 0.f);
    for (size_t i = (size_t)blockIdx.x * blockDim.x + threadIdx.x; i < n4;
         i += (size_t)gridDim.x * blockDim.x) {
        reinterpret_cast<float4*>(g_s)[i] = z;
        reinterpret_cast<float4*>(g_r)[i] = z;
    }
}

// MODE 0: pairs  A=[h_ki | mess[nei]] @ Wr ; epi: sigmoid, v4-red(r*mess -> g_r[src]);
//                plus v4-red(mess -> g_s[src]) pre-pass (n-chunk partitioned)
// MODE 1: bonds  A=[h_ij | g_s] @ Wz ; epi: g_z = sigmoid
// MODE 2: bonds  A=[h_ij | g_r] @ [W;U] ; epi: out = (1-z)*s + z*tanh
template <int MODE>
__global__ __launch_bounds__(256, 2)
void dmpnn_mma(const float* __restrict__ h_ij, const float* __restrict__ h_ki,
               const float* __restrict__ mess,
               const int* __restrict__ src_idx, const int* __restrict__ nei_idx,
               const float* __restrict__ Wz_w, const float* __restrict__ Wz_b,
               const float* __restrict__ Wr_w, const float* __restrict__ Wr_b,
               const float* __restrict__ U_w,
               const float* __restrict__ W_w, const float* __restrict__ W_b,
               float* __restrict__ out)
{
    __shared__ float As[2][128][20];    // [stage][m][k] stride 20 (conflict-free frags)
    __shared__ float Bs[2][16][136];    // [stage][k][n] stride 136
    __shared__ int s_src[128], s_nei[128];

    const int tid  = threadIdx.x;
    const int warp = tid >> 5;
    const int lane = tid & 31;
    const int wr   = warp & 3;          // warp row (4)
    const int wc   = warp >> 2;         // warp col (2)
    const int gid  = lane >> 2;         // 0..7
    const int tig  = lane & 3;          // 0..3
    const int r0   = blockIdx.x * 128;
    const int n0   = blockIdx.y * 128;

    if (MODE == 0 && tid < 128) {
        s_src[tid] = src_idx[r0 + tid];
        s_nei[tid] = nei_idx[r0 + tid];
    }
    __syncthreads();

    const uint32_t aSm[2] = { smem_u32(&As[0][0][0]), smem_u32(&As[1][0][0]) };
    const uint32_t bSm[2] = { smem_u32(&Bs[0][0][0]), smem_u32(&Bs[1][0][0]) };

    // ---- stage fill via cp.async (A: 128x16, B: 16x128) ----
    auto fill = [&](int s) {
        const int st = s & 1;
        const int k0 = s * 16;
#pragma unroll
        for (int i = 0; i < 2; ++i) {
            int idx = tid + 256 * i;
            int row = idx >> 2, kq = idx & 3;
            const float* ap;
            if (MODE == 0)
                ap = (k0 < FNB) ? h_ki + (size_t)(r0 + row) * FNB + k0 + kq * 4
                                : mess + (size_t)s_nei[row] * DM + (k0 - FNB) + kq * 4;
            else if (MODE == 1)
                ap = (k0 < FNB) ? h_ij + (size_t)(r0 + row) * FNB + k0 + kq * 4
                                : g_s + (size_t)(r0 + row) * DM + (k0 - FNB) + kq * 4;
            else
                ap = (k0 < FNB) ? h_ij + (size_t)(r0 + row) * FNB + k0 + kq * 4
                                : g_r + (size_t)(r0 + row) * DM + (k0 - FNB) + kq * 4;
            cpasync16(aSm[st] + row * 80 + kq * 16, ap);
        }
#pragma unroll
        for (int i = 0; i < 2; ++i) {
            int idx = tid + 256 * i;
            int row = idx >> 5, c = idx & 31;
            const float* bp;
            if (MODE == 0)      bp = Wr_w + (size_t)(k0 + row) * DM + n0 + c * 4;
            else if (MODE == 1) bp = Wz_w + (size_t)(k0 + row) * DM + n0 + c * 4;
            else bp = (k0 < FNB) ? W_w + (size_t)(k0 + row) * DM + n0 + c * 4
                                 : U_w + (size_t)(k0 + row - FNB) * DM + n0 + c * 4;
            cpasync16(bSm[st] + row * 544 + c * 16, bp);
        }
        CP_COMMIT();
    };

    float acc[2][8][4];
#pragma unroll
    for (int mt = 0; mt < 2; ++mt)
#pragma unroll
        for (int nt = 0; nt < 8; ++nt)
#pragma unroll
            for (int q = 0; q < 4; ++q) acc[mt][nt][q] = 0.f;

    fill(0);

    if (MODE == 0) {
        // s_ij scatter for cols [n0, n0+128) — overlaps with fill(0) latency
        for (int it = tid; it < 128 * 32; it += 256) {
            int row = it >> 5, c = (it & 31) << 2;
            const float4 v = *(const float4*)(mess + (size_t)s_nei[row] * DM + n0 + c);
            red4(g_s + (size_t)s_src[row] * DM + n0 + c, v.x, v.y, v.z, v.w);
        }
    }

#pragma unroll 1
    for (int s = 0; s < NST; ++s) {
        if (s + 1 < NST) {
            fill(s + 1);
            asm volatile("cp.async.wait_group 1;" ::: "memory");
        } else {
            asm volatile("cp.async.wait_group 0;" ::: "memory");
        }
        __syncthreads();
        const int st = s & 1;
#pragma unroll
        for (int kh = 0; kh < 2; ++kh) {
            const int kk = kh * 8;
            uint32_t af[2][4];
#pragma unroll
            for (int mt = 0; mt < 2; ++mt) {
                int rb = wr * 32 + mt * 16;
                af[mt][0] = to_tf32(As[st][rb + gid][kk + tig]);
                af[mt][1] = to_tf32(As[st][rb + gid + 8][kk + tig]);
                af[mt][2] = to_tf32(As[st][rb + gid][kk + tig + 4]);
                af[mt][3] = to_tf32(As[st][rb + gid + 8][kk + tig + 4]);
            }
            uint32_t bf[8][2];
#pragma unroll
            for (int nt = 0; nt < 8; ++nt) {
                int cb = wc * 64 + nt * 8;
                bf[nt][0] = to_tf32(Bs[st][kk + tig][cb + gid]);
                bf[nt][1] = to_tf32(Bs[st][kk + tig + 4][cb + gid]);
            }
#pragma unroll
            for (int mt = 0; mt < 2; ++mt)
#pragma unroll
                for (int nt = 0; nt < 8; ++nt)
                    MMA8(acc[mt][nt], af[mt], bf[nt]);
        }
        __syncthreads();
    }

    // ---- epilogue ----
    // c0,c1 at (row=gid, cols 2tig,2tig+1), c2,c3 at row=gid+8
#pragma unroll
    for (int mt = 0; mt < 2; ++mt) {
#pragma unroll
        for (int half = 0; half < 2; ++half) {
            const int lr = wr * 32 + mt * 16 + gid + half * 8;  // local row
            const int gm = r0 + lr;
            if (MODE == 0) {
                const float* mrow = mess + (size_t)s_nei[lr] * DM;
                float* rdst = g_r + (size_t)s_src[lr] * DM;
#pragma unroll
                for (int nt = 0; nt < 8; ++nt) {
                    const int n = n0 + wc * 64 + nt * 8 + 2 * tig;
                    float v0 = acc[mt][nt][half * 2 + 0];
                    float v1 = acc[mt][nt][half * 2 + 1];
                    float2 bb = *(const float2*)(Wr_b + n);
                    float2 m2 = *(const float2*)(mrow + n);
                    float p0 = sigmoidf_(v0 + bb.x) * m2.x;
                    float p1 = sigmoidf_(v1 + bb.y) * m2.y;
                    // merge quad neighbors: even-tig lanes issue v4 reds
                    float q0 = __shfl_down_sync(0xffffffffu, p0, 1);
                    float q1 = __shfl_down_sync(0xffffffffu, p1, 1);
                    if ((tig & 1) == 0)
                        red4(rdst + n, p0, p1, q0, q1);
                }
            } else if (MODE == 1) {
#pragma unroll
                for (int nt = 0; nt < 8; ++nt) {
                    const int n = n0 + wc * 64 + nt * 8 + 2 * tig;
                    float2 bb = *(const float2*)(Wz_b + n);
                    float2 zz;
                    zz.x = sigmoidf_(acc[mt][nt][half * 2 + 0] + bb.x);
                    zz.y = sigmoidf_(acc[mt][nt][half * 2 + 1] + bb.y);
                    *(float2*)(g_z + (size_t)gm * DM + n) = zz;
                }
            } else {
#pragma unroll
                for (int nt = 0; nt < 8; ++nt) {
                    const int n = n0 + wc * 64 + nt * 8 + 2 * tig;
                    float2 bb = *(const float2*)(W_b + n);
                    float2 z2 = *(const float2*)(g_z + (size_t)gm * DM + n);
                    float2 s2 = *(const float2*)(g_s + (size_t)gm * DM + n);
                    float2 o;
                    o.x = (1.f - z2.x) * s2.x +
                          z2.x * tanhf(acc[mt][nt][half * 2 + 0] + bb.x);
                    o.y = (1.f - z2.y) * s2.y +
                          z2.y * tanhf(acc[mt][nt][half * 2 + 1] + bb.y);
                    *(float2*)(out + (size_t)gm * DM + n) = o;
                }
            }
        }
    }
}

// ---------------- launch ----------------
extern "C" void kernel_launch(void* const* d_in, const int* in_sizes, int n_in,
                              void* d_out, int out_size) {
    const float* h_ij = (const float*)d_in[0];
    const float* h_ki = (const float*)d_in[1];
    const float* mess = (const float*)d_in[2];
    const int* src_i  = (const int*)d_in[3];
    const int* nei_i  = (const int*)d_in[4];
    const float* Wz_w = (const float*)d_in[5];
    const float* Wz_b = (const float*)d_in[6];
    const float* Wr_w = (const float*)d_in[7];
    const float* Wr_b = (const float*)d_in[8];
    const float* U_w  = (const float*)d_in[9];
    const float* W_w  = (const float*)d_in[10];
    const float* W_b  = (const float*)d_in[11];
    float* out = (float*)d_out;

    zero_scratch<<<1184, 256>>>();

    dim3 g0(MP / 128, 2);
    dmpnn_mma<0><<<g0, 256>>>(h_ij, h_ki, mess, src_i, nei_i,
                              Wz_w, Wz_b, Wr_w, Wr_b, U_w, W_w, W_b, out);
    dim3 g1(EB / 128, 2);
    dmpnn_mma<1><<<g1, 256>>>(h_ij, h_ki, mess, src_i, nei_i,
                              Wz_w, Wz_b, Wr_w, Wr_b, U_w, W_w, W_b, out);
    dmpnn_mma<2><<<g1, 256>>>(h_ij, h_ki, mess, src_i, nei_i,
                              Wz_w, Wz_b, Wr_w, Wr_b, U_w, W_w, W_b, out);
}

// round 15
// speedup vs baseline: 1.0060x; 1.0021x over previous
#include <cuda_runtime.h>
#include <math.h>
#include <stdint.h>

#define EB 262144
#define MP 786432
#define FNB 192
#define DM 256
#define KT 448
#define NST 28            // 448 / 16 k-stages

// ---- scratch ----
__device__ float g_s[(size_t)EB * DM];
__device__ float g_r[(size_t)EB * DM];
__device__ float g_z[(size_t)EB * DM];

// ---------------- helpers ----------------
__device__ __forceinline__ uint32_t smem_u32(const void* p) {
    uint32_t a;
    asm("{ .reg .u64 t; cvta.to.shared.u64 t, %1; cvt.u32.u64 %0, t; }" : "=r"(a) : "l"(p));
    return a;
}
__device__ __forceinline__ uint32_t to_tf32(float f) {
    uint32_t r;
    asm("cvt.rna.tf32.f32 %0, %1;" : "=r"(r) : "f"(f));
    return r;
}
__device__ __forceinline__ void red4(float* p, float a, float b, float c, float d) {
    asm volatile("red.global.add.v4.f32 [%0], {%1,%2,%3,%4};"
                 :: "l"(p), "f"(a), "f"(b), "f"(c), "f"(d) : "memory");
}
__device__ __forceinline__ void cpasync16(uint32_t dst, const void* src) {
    asm volatile("cp.async.cg.shared.global [%0], [%1], 16;" :: "r"(dst), "l"(src) : "memory");
}
#define CP_COMMIT() asm volatile("cp.async.commit_group;" ::: "memory")

__device__ __forceinline__ float sigmoidf_(float x) { return 1.f / (1.f + __expf(-x)); }

#define MMA8(d, a, b)                                                           \
    asm volatile("mma.sync.aligned.m16n8k8.row.col.f32.tf32.tf32.f32 "          \
                 "{%0,%1,%2,%3}, {%4,%5,%6,%7}, {%8,%9}, {%0,%1,%2,%3};"        \
                 : "+f"((d)[0]), "+f"((d)[1]), "+f"((d)[2]), "+f"((d)[3])       \
                 : "r"((a)[0]), "r"((a)[1]), "r"((a)[2]), "r"((a)[3]),          \
                   "r"((b)[0]), "r"((b)[1]))

__global__ void zero_scratch() {
    size_t n4 = ((size_t)EB * DM) / 4;
    float4 z = make_float4(0.f, 0.f, 0.f, 0.f);
    for (size_t i = (size_t)blockIdx.x * blockDim.x + threadIdx.x; i < n4;
         i += (size_t)gridDim.x * blockDim.x) {
        reinterpret_cast<float4*>(g_s)[i] = z;
        reinterpret_cast<float4*>(g_r)[i] = z;
    }
}

// MODE 0: pairs  A=[h_ki | mess[nei]] @ Wr ; epi: sigmoid, v4-red(r*mess -> g_r[src]);
//                plus v4-red(mess -> g_s[src]) pre-pass (n-chunk partitioned)
// MODE 1: bonds  A=[h_ij | g_s] @ Wz ; epi: g_z = sigmoid
// MODE 2: bonds  A=[h_ij | g_r] @ [W;U] ; epi: out = (1-z)*s + z*tanh
template <int MODE>
__global__ __launch_bounds__(256, 2)
void dmpnn_mma(const float* __restrict__ h_ij, const float* __restrict__ h_ki,
               const float* __restrict__ mess,
               const int* __restrict__ src_idx, const int* __restrict__ nei_idx,
               const float* __restrict__ Wz_w, const float* __restrict__ Wz_b,
               const float* __restrict__ Wr_w, const float* __restrict__ Wr_b,
               const float* __restrict__ U_w,
               const float* __restrict__ W_w, const float* __restrict__ W_b,
               float* __restrict__ out)
{
    __shared__ float As[2][128][20];    // [stage][m][k] stride 20 (conflict-free frags)
    __shared__ float Bs[2][16][136];    // [stage][k][n] stride 136
    __shared__ int s_src[128], s_nei[128];

    const int tid  = threadIdx.x;
    const int warp = tid >> 5;
    const int lane = tid & 31;
    const int wr   = warp & 3;          // warp row (4)
    const int wc   = warp >> 2;         // warp col (2)
    const int gid  = lane >> 2;         // 0..7
    const int tig  = lane & 3;          // 0..3
    const int r0   = blockIdx.x * 128;
    const int n0   = blockIdx.y * 128;

    if (MODE == 0 && tid < 128) {
        s_src[tid] = src_idx[r0 + tid];
        s_nei[tid] = nei_idx[r0 + tid];
    }
    __syncthreads();

    const uint32_t aSm[2] = { smem_u32(&As[0][0][0]), smem_u32(&As[1][0][0]) };
    const uint32_t bSm[2] = { smem_u32(&Bs[0][0][0]), smem_u32(&Bs[1][0][0]) };

    // ---- stage fill via cp.async (A: 128x16, B: 16x128) ----
    auto fill = [&](int s) {
        const int st = s & 1;
        const int k0 = s * 16;
#pragma unroll
        for (int i = 0; i < 2; ++i) {
            int idx = tid + 256 * i;
            int row = idx >> 2, kq = idx & 3;
            const float* ap;
            if (MODE == 0)
                ap = (k0 < FNB) ? h_ki + (size_t)(r0 + row) * FNB + k0 + kq * 4
                                : mess + (size_t)s_nei[row] * DM + (k0 - FNB) + kq * 4;
            else if (MODE == 1)
                ap = (k0 < FNB) ? h_ij + (size_t)(r0 + row) * FNB + k0 + kq * 4
                                : g_s + (size_t)(r0 + row) * DM + (k0 - FNB) + kq * 4;
            else
                ap = (k0 < FNB) ? h_ij + (size_t)(r0 + row) * FNB + k0 + kq * 4
                                : g_r + (size_t)(r0 + row) * DM + (k0 - FNB) + kq * 4;
            cpasync16(aSm[st] + row * 80 + kq * 16, ap);
        }
#pragma unroll
        for (int i = 0; i < 2; ++i) {
            int idx = tid + 256 * i;
            int row = idx >> 5, c = idx & 31;
            const float* bp;
            if (MODE == 0)      bp = Wr_w + (size_t)(k0 + row) * DM + n0 + c * 4;
            else if (MODE == 1) bp = Wz_w + (size_t)(k0 + row) * DM + n0 + c * 4;
            else bp = (k0 < FNB) ? W_w + (size_t)(k0 + row) * DM + n0 + c * 4
                                 : U_w + (size_t)(k0 + row - FNB) * DM + n0 + c * 4;
            cpasync16(bSm[st] + row * 544 + c * 16, bp);
        }
        CP_COMMIT();
    };

    float acc[2][8][4];
#pragma unroll
    for (int mt = 0; mt < 2; ++mt)
#pragma unroll
        for (int nt = 0; nt < 8; ++nt)
#pragma unroll
            for (int q = 0; q < 4; ++q) acc[mt][nt][q] = 0.f;

    fill(0);

    if (MODE == 0) {
        // s_ij scatter for cols [n0, n0+128) — overlaps with fill(0) latency
        for (int it = tid; it < 128 * 32; it += 256) {
            int row = it >> 5, c = (it & 31) << 2;
            const float4 v = *(const float4*)(mess + (size_t)s_nei[row] * DM + n0 + c);
            red4(g_s + (size_t)s_src[row] * DM + n0 + c, v.x, v.y, v.z, v.w);
        }
    }

#pragma unroll 1
    for (int s = 0; s < NST; ++s) {
        if (s + 1 < NST) {
            fill(s + 1);
            asm volatile("cp.async.wait_group 1;" ::: "memory");
        } else {
            asm volatile("cp.async.wait_group 0;" ::: "memory");
        }
        __syncthreads();
        const int st = s & 1;
#pragma unroll
        for (int kh = 0; kh < 2; ++kh) {
            const int kk = kh * 8;
            uint32_t af[2][4];
#pragma unroll
            for (int mt = 0; mt < 2; ++mt) {
                int rb = wr * 32 + mt * 16;
                af[mt][0] = to_tf32(As[st][rb + gid][kk + tig]);
                af[mt][1] = to_tf32(As[st][rb + gid + 8][kk + tig]);
                af[mt][2] = to_tf32(As[st][rb + gid][kk + tig + 4]);
                af[mt][3] = to_tf32(As[st][rb + gid + 8][kk + tig + 4]);
            }
            uint32_t bf[8][2];
#pragma unroll
            for (int nt = 0; nt < 8; ++nt) {
                int cb = wc * 64 + nt * 8;
                bf[nt][0] = to_tf32(Bs[st][kk + tig][cb + gid]);
                bf[nt][1] = to_tf32(Bs[st][kk + tig + 4][cb + gid]);
            }
#pragma unroll
            for (int mt = 0; mt < 2; ++mt)
#pragma unroll
                for (int nt = 0; nt < 8; ++nt)
                    MMA8(acc[mt][nt], af[mt], bf[nt]);
        }
        __syncthreads();
    }

    // ---- epilogue ----
    // c0,c1 at (row=gid, cols 2tig,2tig+1), c2,c3 at row=gid+8
#pragma unroll
    for (int mt = 0; mt < 2; ++mt) {
#pragma unroll
        for (int half = 0; half < 2; ++half) {
            const int lr = wr * 32 + mt * 16 + gid + half * 8;  // local row
            const int gm = r0 + lr;
            if (MODE == 0) {
                const float* mrow = mess + (size_t)s_nei[lr] * DM;
                float* rdst = g_r + (size_t)s_src[lr] * DM;
#pragma unroll
                for (int nt = 0; nt < 8; ++nt) {
                    const int n = n0 + wc * 64 + nt * 8 + 2 * tig;
                    float v0 = acc[mt][nt][half * 2 + 0];
                    float v1 = acc[mt][nt][half * 2 + 1];
                    float2 bb = *(const float2*)(Wr_b + n);
                    float2 m2 = *(const float2*)(mrow + n);
                    float p0 = sigmoidf_(v0 + bb.x) * m2.x;
                    float p1 = sigmoidf_(v1 + bb.y) * m2.y;
                    // merge quad neighbors: even-tig lanes issue v4 reds
                    float q0 = __shfl_down_sync(0xffffffffu, p0, 1);
                    float q1 = __shfl_down_sync(0xffffffffu, p1, 1);
                    if ((tig & 1) == 0)
                        red4(rdst + n, p0, p1, q0, q1);
                }
            } else if (MODE == 1) {
#pragma unroll
                for (int nt = 0; nt < 8; ++nt) {
                    const int n = n0 + wc * 64 + nt * 8 + 2 * tig;
                    float2 bb = *(const float2*)(Wz_b + n);
                    float2 zz;
                    zz.x = sigmoidf_(acc[mt][nt][half * 2 + 0] + bb.x);
                    zz.y = sigmoidf_(acc[mt][nt][half * 2 + 1] + bb.y);
                    *(float2*)(g_z + (size_t)gm * DM + n) = zz;
                }
            } else {
#pragma unroll
                for (int nt = 0; nt < 8; ++nt) {
                    const int n = n0 + wc * 64 + nt * 8 + 2 * tig;
                    float2 bb = *(const float2*)(W_b + n);
                    float2 z2 = *(const float2*)(g_z + (size_t)gm * DM + n);
                    float2 s2 = *(const float2*)(g_s + (size_t)gm * DM + n);
                    float2 o;
                    o.x = (1.f - z2.x) * s2.x +
                          z2.x * tanhf(acc[mt][nt][half * 2 + 0] + bb.x);
                    o.y = (1.f - z2.y) * s2.y +
                          z2.y * tanhf(acc[mt][nt][half * 2 + 1] + bb.y);
                    *(float2*)(out + (size_t)gm * DM + n) = o;
                }
            }
        }
    }
}

// ---------------- launch ----------------
extern "C" void kernel_launch(void* const* d_in, const int* in_sizes, int n_in,
                              void* d_out, int out_size) {
    const float* h_ij = (const float*)d_in[0];
    const float* h_ki = (const float*)d_in[1];
    const float* mess = (const float*)d_in[2];
    const int* src_i  = (const int*)d_in[3];
    const int* nei_i  = (const int*)d_in[4];
    const float* Wz_w = (const float*)d_in[5];
    const float* Wz_b = (const float*)d_in[6];
    const float* Wr_w = (const float*)d_in[7];
    const float* Wr_b = (const float*)d_in[8];
    const float* U_w  = (const float*)d_in[9];
    const float* W_w  = (const float*)d_in[10];
    const float* W_b  = (const float*)d_in[11];
    float* out = (float*)d_out;

    zero_scratch<<<1184, 256>>>();

    dim3 g0(MP / 128, 2);
    dmpnn_mma<0><<<g0, 256>>>(h_ij, h_ki, mess, src_i, nei_i,
                              Wz_w, Wz_b, Wr_w, Wr_b, U_w, W_w, W_b, out);
    dim3 g1(EB / 128, 2);
    dmpnn_mma<1><<<g1, 256>>>(h_ij, h_ki, mess, src_i, nei_i,
                              Wz_w, Wz_b, Wr_w, Wr_b, U_w, W_w, W_b, out);
    dmpnn_mma<2><<<g1, 256>>>(h_ij, h_ki, mess, src_i, nei_i,
                              Wz_w, Wz_b, Wr_w, Wr_b, U_w, W_w, W_b, out);
}